// round 1
// baseline (speedup 1.0000x reference)
#include <cuda_runtime.h>

// AlphaGridMask: stable counting-sort by block id + trilinear grid_sample.
// N = 4,194,304 points, 64 blocks, volume 256^3 f32 viewed as [64][64][64][64].

#define SPT   64                 // points per thread (contiguous segment)
#define NBIN  64
#define MAX_NT 65536             // 4194304 / 64

// Scratch (static device globals — no runtime allocation).
__device__ unsigned int g_counts[NBIN * MAX_NT];   // 16 MB: hist -> exclusive prefix (bin-major)
__device__ unsigned int g_totals[NBIN];
__device__ unsigned int g_binbase[NBIN];

// Bit-exact block id vs reference: IEEE sub, IEEE div, floor, clip to [0,3].
__device__ __forceinline__ int bid_of(float x, float y, float z,
                                      float a0x, float a0y, float a0z,
                                      float vx, float vy, float vz) {
    float qx = __fdiv_rn(x - a0x, vx);
    float qy = __fdiv_rn(y - a0y, vy);
    float qz = __fdiv_rn(z - a0z, vz);
    int ix = (int)floorf(qx);
    int iy = (int)floorf(qy);
    int iz = (int)floorf(qz);
    ix = min(max(ix, 0), 3);
    iy = min(max(iy, 0), 3);
    iz = min(max(iz, 0), 3);
    return (ix << 4) + (iy << 2) + iz;   // strides [16,4,1]
}

// ---------------- Pass 1: per-thread histograms ----------------
__global__ void __launch_bounds__(128) k_count(const float* __restrict__ xyz,
                                               const float* __restrict__ aabb,
                                               int nt) {
    int t = blockIdx.x * blockDim.x + threadIdx.x;
    if (t >= nt) return;
    float a0x = __ldg(aabb + 0), a0y = __ldg(aabb + 1), a0z = __ldg(aabb + 2);
    float vx = (__ldg(aabb + 3) - a0x) * 0.25f;   // (aabb1-aabb0)/4, /4 exact
    float vy = (__ldg(aabb + 4) - a0y) * 0.25f;
    float vz = (__ldg(aabb + 5) - a0z) * 0.25f;

    unsigned char hist[NBIN];
    #pragma unroll
    for (int b = 0; b < NBIN; b++) hist[b] = 0;

    const float* p = xyz + (size_t)t * SPT * 3;
    #pragma unroll 4
    for (int k = 0; k < SPT; k++) {
        float x = __ldg(p + 3 * k + 0);
        float y = __ldg(p + 3 * k + 1);
        float z = __ldg(p + 3 * k + 2);
        hist[bid_of(x, y, z, a0x, a0y, a0z, vx, vy, vz)]++;
    }
    #pragma unroll
    for (int b = 0; b < NBIN; b++)
        g_counts[(size_t)b * nt + t] = hist[b];   // coalesced across t
}

// ---------------- Pass 2a: per-bin exclusive scan (64 CTAs) ----------------
__global__ void __launch_bounds__(512) k_scan_row(int nt) {
    int b = blockIdx.x, tid = threadIdx.x;
    int per = nt >> 9;                         // nt / 512 (nt = 65536 -> 128)
    unsigned int* row = g_counts + (size_t)b * nt;
    int base = tid * per;

    unsigned int s = 0;
    for (int k = 0; k < per; k++) s += row[base + k];

    __shared__ unsigned int sh[512];
    sh[tid] = s;
    __syncthreads();
    for (int off = 1; off < 512; off <<= 1) {
        unsigned int v = 0;
        if (tid >= off) v = sh[tid - off];
        __syncthreads();
        if (tid >= off) sh[tid] += v;
        __syncthreads();
    }
    unsigned int incl = sh[tid];
    if (tid == 511) g_totals[b] = incl;

    unsigned int run = incl - s;               // exclusive base for this thread
    for (int k = 0; k < per; k++) {
        unsigned int v = row[base + k];
        row[base + k] = run;
        run += v;
    }
}

// ---------------- Pass 2b: scan the 64 bin totals ----------------
__global__ void k_scan_bins() {
    int tid = threadIdx.x;
    unsigned int v = g_totals[tid];
    __shared__ unsigned int sh[64];
    sh[tid] = v;
    __syncthreads();
    for (int off = 1; off < 64; off <<= 1) {
        unsigned int u = 0;
        if (tid >= off) u = sh[tid - off];
        __syncthreads();
        if (tid >= off) sh[tid] += u;
        __syncthreads();
    }
    g_binbase[tid] = sh[tid] - v;
}

// ---------------- Pass 3: sample + scatter to stable-sorted slots ----------------
__global__ void __launch_bounds__(128) k_sample(const float* __restrict__ xyz,
                                                const float* __restrict__ aabb,
                                                const float* __restrict__ vol,
                                                const float* __restrict__ dmin,
                                                const float* __restrict__ dmax,
                                                float* __restrict__ out,
                                                int nt) {
    __shared__ float s_dmin[192], s_dmax[192], s_bb[6];
    __shared__ unsigned int s_base[NBIN];
    int tid = threadIdx.x;
    for (int i = tid; i < 192; i += blockDim.x) { s_dmin[i] = dmin[i]; s_dmax[i] = dmax[i]; }
    if (tid < 6)  s_bb[tid] = aabb[tid];
    if (tid < NBIN) s_base[tid] = g_binbase[tid];
    __syncthreads();

    int t = blockIdx.x * blockDim.x + tid;
    if (t >= nt) return;

    unsigned int offs[NBIN];                   // running destination per bin (local mem)
    #pragma unroll
    for (int b = 0; b < NBIN; b++)
        offs[b] = s_base[b] + g_counts[(size_t)b * nt + t];

    float a0x = s_bb[0], a0y = s_bb[1], a0z = s_bb[2];
    float vx = (s_bb[3] - a0x) * 0.25f;
    float vy = (s_bb[4] - a0y) * 0.25f;
    float vz = (s_bb[5] - a0z) * 0.25f;

    const float* p = xyz + (size_t)t * SPT * 3;
    for (int k = 0; k < SPT; k++) {
        float x = __ldg(p + 3 * k + 0);
        float y = __ldg(p + 3 * k + 1);
        float z = __ldg(p + 3 * k + 2);
        int bid = bid_of(x, y, z, a0x, a0y, a0z, vx, vy, vz);
        int b3 = bid * 3;

        // local = 2*(p-dmin)/(dmax-dmin) - 1 ; f = (local+1)*0.5*63
        float lx = 2.0f * (x - s_dmin[b3 + 0]) / (s_dmax[b3 + 0] - s_dmin[b3 + 0]) - 1.0f;
        float ly = 2.0f * (y - s_dmin[b3 + 1]) / (s_dmax[b3 + 1] - s_dmin[b3 + 1]) - 1.0f;
        float lz = 2.0f * (z - s_dmin[b3 + 2]) / (s_dmax[b3 + 2] - s_dmin[b3 + 2]) - 1.0f;
        float fx = (lx + 1.0f) * 0.5f * 63.0f;
        float fy = (ly + 1.0f) * 0.5f * 63.0f;
        float fz = (lz + 1.0f) * 0.5f * 63.0f;

        float x0f = floorf(fx), y0f = floorf(fy), z0f = floorf(fz);
        float wx = fx - x0f, wy = fy - y0f, wz = fz - z0f;
        int x0 = (int)x0f, y0 = (int)y0f, z0 = (int)z0f;

        int x0c = min(max(x0, 0), 63), x1c = min(max(x0 + 1, 0), 63);
        int y0c = min(max(y0, 0), 63), y1c = min(max(y0 + 1, 0), 63);
        int z0c = min(max(z0, 0), 63), z1c = min(max(z0 + 1, 0), 63);

        const float* vb = vol + ((size_t)bid << 18);   // 64^3 floats per block
        int zy00 = ((z0c << 6) + y0c) << 6;
        int zy01 = ((z0c << 6) + y1c) << 6;
        int zy10 = ((z1c << 6) + y0c) << 6;
        int zy11 = ((z1c << 6) + y1c) << 6;

        float v000 = __ldg(vb + zy00 + x0c), v001 = __ldg(vb + zy00 + x1c);
        float v010 = __ldg(vb + zy01 + x0c), v011 = __ldg(vb + zy01 + x1c);
        float v100 = __ldg(vb + zy10 + x0c), v101 = __ldg(vb + zy10 + x1c);
        float v110 = __ldg(vb + zy11 + x0c), v111 = __ldg(vb + zy11 + x1c);

        float omx = 1.0f - wx, omy = 1.0f - wy, omz = 1.0f - wz;
        float r = omz * (omy * (omx * v000 + wx * v001) + wy * (omx * v010 + wx * v011))
                + wz  * (omy * (omx * v100 + wx * v101) + wy * (omx * v110 + wx * v111));

        unsigned int d = offs[bid]++;
        out[d] = r;
    }
}

extern "C" void kernel_launch(void* const* d_in, const int* in_sizes, int n_in,
                              void* d_out, int out_size) {
    const float* xyz  = (const float*)d_in[0];
    const float* aabb = (const float*)d_in[1];
    const float* vol  = (const float*)d_in[2];
    const float* dmin = (const float*)d_in[3];
    const float* dmax = (const float*)d_in[4];
    float* out = (float*)d_out;

    int n  = in_sizes[0] / 3;         // 4,194,304
    int nt = n / SPT;                 // 65,536 threads

    int grid = (nt + 127) / 128;
    k_count<<<grid, 128>>>(xyz, aabb, nt);
    k_scan_row<<<NBIN, 512>>>(nt);
    k_scan_bins<<<1, NBIN>>>();
    k_sample<<<grid, 128>>>(xyz, aabb, vol, dmin, dmax, out, nt);
}